// round 2
// baseline (speedup 1.0000x reference)
#include <cuda_runtime.h>
#include <cstdint>

// Problem constants
#define B 8
#define N 4096
#define C 1024
#define H 16
#define D 64
#define SCALE 0.125f

// Scratch (no cudaMalloc allowed)
__device__ float g_k[B * C];       // [b][h*D+d]
__device__ float g_v[B * C];
__device__ float g_u[B * H * C];   // [b][h][c]  folded Wq*k
__device__ float g_M[B * H * C];   // [b][h][c]  folded Wp*v

// Packed fp32x2 helpers (sm_103a)
#define FMA2(acc, a, bb) asm("fma.rn.f32x2 %0, %1, %2, %0;" : "+l"(acc) : "l"(a), "l"(bb))
#define ADD2(d, a, bb)   asm("add.rn.f32x2 %0, %1, %2;"     : "=l"(d)   : "l"(a), "l"(bb))

// ---------------------------------------------------------------------------
// P1: k = emb @ Wk.T, v = emb @ Wv.T   (warp per output j, all 8 batches)
// grid: 256 blocks x 256 thr  (2048 warps = 2 mats * 1024 rows)
// ---------------------------------------------------------------------------
__global__ void __launch_bounds__(256) precompute_kv(
    const float* __restrict__ emb, const float* __restrict__ Wk,
    const float* __restrict__ Wv) {
  int gw = (blockIdx.x * 256 + threadIdx.x) >> 5;
  int lane = threadIdx.x & 31;
  const float* W = (gw < 1024) ? Wk : Wv;
  float* dst = (gw < 1024) ? g_k : g_v;
  int j = gw & 1023;
  const float4* w4 = reinterpret_cast<const float4*>(W + j * C);
  const float4* e4 = reinterpret_cast<const float4*>(emb);
  float acc[B];
#pragma unroll
  for (int b = 0; b < B; b++) acc[b] = 0.f;
#pragma unroll
  for (int i = 0; i < 8; i++) {
    float4 wv = w4[lane + 32 * i];
#pragma unroll
    for (int b = 0; b < B; b++) {
      float4 e = e4[b * 256 + lane + 32 * i];
      acc[b] += wv.x * e.x + wv.y * e.y + wv.z * e.z + wv.w * e.w;
    }
  }
#pragma unroll
  for (int b = 0; b < B; b++)
    for (int s = 16; s; s >>= 1) acc[b] += __shfl_xor_sync(0xffffffffu, acc[b], s);
  if (lane == 0) {
#pragma unroll
    for (int b = 0; b < B; b++) dst[b * C + j] = acc[b];
  }
}

// ---------------------------------------------------------------------------
// P2: u[b,h,c] = sum_d Wq[h*64+d, c] * k[b,h*64+d]
//     M[b,h,c] = sum_d Wp[c, h*64+d] * v[b,h*64+d]
// grid: (4, 16) x 256 thr; thread owns one c, loops all 8 batches
// ---------------------------------------------------------------------------
__global__ void __launch_bounds__(256) precompute_uM(
    const float* __restrict__ Wq, const float* __restrict__ Wp) {
  __shared__ float kk[B][D];
  __shared__ float vv[B][D];
  int h = blockIdx.y;
  int c = blockIdx.x * 256 + threadIdx.x;
  for (int i = threadIdx.x; i < B * D; i += 256) {
    int b = i >> 6, d = i & 63;
    kk[b][d] = g_k[b * C + h * D + d];
    vv[b][d] = g_v[b * C + h * D + d];
  }
  __syncthreads();

  float acc[B];
#pragma unroll
  for (int b = 0; b < B; b++) acc[b] = 0.f;
#pragma unroll 8
  for (int d = 0; d < D; d++) {
    float wq = Wq[(h * D + d) * C + c];
#pragma unroll
    for (int b = 0; b < B; b++) acc[b] += wq * kk[b][d];
  }
#pragma unroll
  for (int b = 0; b < B; b++) g_u[(b * H + h) * C + c] = acc[b];

  float acc2[B];
#pragma unroll
  for (int b = 0; b < B; b++) acc2[b] = 0.f;
  const float4* wp4 = reinterpret_cast<const float4*>(Wp + c * C + h * D);
#pragma unroll
  for (int i = 0; i < 16; i++) {
    float4 wv = wp4[i];
#pragma unroll
    for (int b = 0; b < B; b++)
      acc2[b] += wv.x * vv[b][i * 4] + wv.y * vv[b][i * 4 + 1] +
                 wv.z * vv[b][i * 4 + 2] + wv.w * vv[b][i * 4 + 3];
  }
#pragma unroll
  for (int b = 0; b < B; b++) g_M[(b * H + h) * C + c] = acc2[b];
}

// ---------------------------------------------------------------------------
// MAIN fused kernel. grid (128, 8), 256 threads, 32-row tile / block.
// Phase 1: scores = fea_tile @ u[b]   (lane = row, warps split C)
// Phase 2: out = fea + bp + attn @ M[b]
// ---------------------------------------------------------------------------
#define ROWS 32
#define FB_STRIDE 260           // floats per staged row (256 + pad 4)
#define FB_SIZE (ROWS * FB_STRIDE)
#define PART_STRIDE 21

__global__ void __launch_bounds__(256, 1) gate_main(
    const float* __restrict__ fea, const float* __restrict__ bp,
    float* __restrict__ out) {
  extern __shared__ __align__(16) float sm[];
  float* u_s = sm;                              // 16384 floats [h][c]
  float* fb = sm + H * C;                       // 2 * FB_SIZE floats
  float* part = fb + 2 * FB_SIZE;               // 8*32*21 floats
  unsigned long long* attn_d =
      reinterpret_cast<unsigned long long*>(part + 8 * ROWS * PART_STRIDE);  // 32*16 ull

  const int b = blockIdx.y;
  const int row0 = blockIdx.x * ROWS;
  const int t = threadIdx.x;
  const int w = t >> 5;
  const int l = t & 31;

  // Load u[b] into smem (L2-resident across blocks)
  {
    const float4* gu4 = reinterpret_cast<const float4*>(g_u + b * H * C);
    float4* us4 = reinterpret_cast<float4*>(u_s);
#pragma unroll
    for (int i = 0; i < 16; i++) us4[t + 256 * i] = gu4[t + 256 * i];
  }

  const float* fea_b = fea + ((size_t)(b * N + row0)) * C;

  // ---- issue cp.async for one 256-col chunk into buffer `buf` ----
#define ISSUE_CHUNK(ck, buf)                                                  \
  {                                                                           \
    _Pragma("unroll") for (int i = 0; i < 8; i++) {                           \
      int idx = t + 256 * i;                                                  \
      int r = idx >> 6;                                                       \
      int c4 = idx & 63;                                                      \
      const float* src = fea_b + r * C + (ck) * 256 + c4 * 4;                 \
      float* dstp = fb + (buf) * FB_SIZE + r * FB_STRIDE + c4 * 4;            \
      unsigned ds = (unsigned)__cvta_generic_to_shared(dstp);                 \
      asm volatile("cp.async.cg.shared.global [%0], [%1], 16;" ::"r"(ds),     \
                   "l"(src));                                                 \
    }                                                                         \
    asm volatile("cp.async.commit_group;" ::: "memory");                      \
  }

  unsigned long long p2[H];
#pragma unroll
  for (int h = 0; h < H; h++) p2[h] = 0ull;

  ISSUE_CHUNK(0, 0);
  ISSUE_CHUNK(1, 1);

#pragma unroll
  for (int ck = 0; ck < 4; ck++) {
    if (ck < 3)
      asm volatile("cp.async.wait_group 1;" ::: "memory");
    else
      asm volatile("cp.async.wait_group 0;" ::: "memory");
    __syncthreads();

    // compute: warp w owns f4 cols [w*8, w*8+8) of this chunk, lane = row
    const float* fbp = fb + (ck & 1) * FB_SIZE + l * FB_STRIDE + w * 32;
#pragma unroll
    for (int j = 0; j < 8; j++) {
      ulonglong2 f = *reinterpret_cast<const ulonglong2*>(fbp + j * 4);
      int c4g = ck * 64 + w * 8 + j;  // global f4 index in row
#pragma unroll
      for (int h = 0; h < H; h++) {
        ulonglong2 uu =
            *reinterpret_cast<const ulonglong2*>(u_s + h * C + c4g * 4);
        FMA2(p2[h], f.x, uu.x);
        FMA2(p2[h], f.y, uu.y);
      }
    }
    __syncthreads();
    if (ck + 2 < 4) ISSUE_CHUNK(ck + 2, ck & 1);
  }

  // write per-warp partials: part[w][row=l][h]
#pragma unroll
  for (int h = 0; h < H; h++) {
    float lo, hi;
    asm("mov.b64 {%0,%1}, %2;" : "=f"(lo), "=f"(hi) : "l"(p2[h]));
    part[(w * ROWS + l) * PART_STRIDE + h] = lo + hi;
  }
  __syncthreads();

  // reduce across 8 warps + sigmoid; store duplicated f32x2 attn
#pragma unroll
  for (int q = 0; q < 2; q++) {
    int p = t + q * 256;     // 0..511 == (r,h)
    int r = p >> 4;
    int h = p & 15;
    float s = 0.f;
#pragma unroll
    for (int ww = 0; ww < 8; ww++) s += part[(ww * ROWS + r) * PART_STRIDE + h];
    float a = 1.f / (1.f + __expf(-s * SCALE));
    unsigned long long ad;
    asm("mov.b64 %0, {%1,%1};" : "=l"(ad) : "f"(a));
    attn_d[r * H + h] = ad;
  }
  __syncthreads();

  // ---- Phase 2: out = fea + bp + attn @ M[b] ; thread owns 4 cols ----
  const int c0 = t * 4;
  ulonglong2 bpv = *reinterpret_cast<const ulonglong2*>(bp + c0);
  ulonglong2 M2[H];
#pragma unroll
  for (int h = 0; h < H; h++)
    M2[h] = *reinterpret_cast<const ulonglong2*>(g_M + (b * H + h) * C + c0);

  float* out_b = out + ((size_t)(b * N + row0)) * C;
#pragma unroll 2
  for (int r = 0; r < ROWS; r++) {
    ulonglong2 f = *reinterpret_cast<const ulonglong2*>(fea_b + r * C + c0);
    unsigned long long oa, ob;
    ADD2(oa, f.x, bpv.x);
    ADD2(ob, f.y, bpv.y);
#pragma unroll
    for (int h = 0; h < H; h++) {
      unsigned long long a = attn_d[r * H + h];
      FMA2(oa, a, M2[h].x);
      FMA2(ob, a, M2[h].y);
    }
    ulonglong2 o;
    o.x = oa;
    o.y = ob;
    *reinterpret_cast<ulonglong2*>(out_b + r * C + c0) = o;
  }
}

// ---------------------------------------------------------------------------
extern "C" void kernel_launch(void* const* d_in, const int* in_sizes, int n_in,
                              void* d_out, int out_size) {
  const float* fea = (const float*)d_in[0];
  const float* emb = (const float*)d_in[1];
  const float* Wq  = (const float*)d_in[2];
  const float* Wk  = (const float*)d_in[3];
  const float* Wv  = (const float*)d_in[4];
  const float* Wp  = (const float*)d_in[5];
  const float* bp  = (const float*)d_in[6];
  float* out = (float*)d_out;

  const int smem_main =
      (H * C + 2 * FB_SIZE + 8 * ROWS * PART_STRIDE) * 4 + ROWS * H * 8;
  cudaFuncSetAttribute(gate_main, cudaFuncAttributeMaxDynamicSharedMemorySize,
                       smem_main);

  precompute_kv<<<256, 256>>>(emb, Wk, Wv);
  precompute_uM<<<dim3(4, 16), 256>>>(Wq, Wp);
  gate_main<<<dim3(N / ROWS, B), 256, smem_main>>>(fea, bp, out);
}

// round 3
// speedup vs baseline: 1.4168x; 1.4168x over previous
#include <cuda_runtime.h>
#include <cstdint>

// Problem constants
#define B 8
#define N 4096
#define C 1024
#define H 16
#define D 64
#define SCALE 0.125f

// Scratch (no cudaMalloc allowed)
__device__ float g_k[B * C];       // [b][h*D+d]
__device__ float g_v[B * C];
__device__ float g_u[B * H * C];   // [b][h][c]  folded Wq*k
__device__ float g_M[B * H * C];   // [b][h][c]  folded Wp*v

// Packed fp32x2 helpers (sm_103a)
#define FMA2(acc, a, bb) asm("fma.rn.f32x2 %0, %1, %2, %0;" : "+l"(acc) : "l"(a), "l"(bb))
#define ADD2(d, a, bb)   asm("add.rn.f32x2 %0, %1, %2;"     : "=l"(d)   : "l"(a), "l"(bb))

// ---------------------------------------------------------------------------
// P1: k = emb @ Wk.T, v = emb @ Wv.T.  Warp per output j; front-batched W row
// loads (4KB in flight per warp) to saturate DRAM.
// ---------------------------------------------------------------------------
__global__ void __launch_bounds__(256) precompute_kv(
    const float* __restrict__ emb, const float* __restrict__ Wk,
    const float* __restrict__ Wv) {
  int gw = (blockIdx.x * 256 + threadIdx.x) >> 5;
  int lane = threadIdx.x & 31;
  const float* W = (gw < 1024) ? Wk : Wv;
  float* dst = (gw < 1024) ? g_k : g_v;
  int j = gw & 1023;
  const float4* w4 = reinterpret_cast<const float4*>(W + j * C);
  const float4* e4 = reinterpret_cast<const float4*>(emb);

  // Front-batch the whole 4KB W row: 8 independent LDG.128 per lane.
  float4 wv[8];
#pragma unroll
  for (int i = 0; i < 8; i++) wv[i] = w4[lane + 32 * i];

  float acc[B];
#pragma unroll
  for (int b = 0; b < B; b++) acc[b] = 0.f;
#pragma unroll
  for (int b = 0; b < B; b++) {
    float4 e[8];
#pragma unroll
    for (int i = 0; i < 8; i++) e[i] = e4[b * 256 + lane + 32 * i];
#pragma unroll
    for (int i = 0; i < 8; i++)
      acc[b] += wv[i].x * e[i].x + wv[i].y * e[i].y + wv[i].z * e[i].z +
                wv[i].w * e[i].w;
  }
#pragma unroll
  for (int b = 0; b < B; b++)
    for (int s = 16; s; s >>= 1) acc[b] += __shfl_xor_sync(0xffffffffu, acc[b], s);
  if (lane == 0) {
#pragma unroll
    for (int b = 0; b < B; b++) dst[b * C + j] = acc[b];
  }
}

// ---------------------------------------------------------------------------
// P2: u[b,h,c] = sum_d Wq[h*64+d, c] * k[b,h*64+d]
//     M[b,h,c] = sum_d Wp[c, h*64+d] * v[b,h*64+d]
// grid (4, 16, 2): x = c-block, y = h, z = batch-group of 4.
// Front-batched load queues for MLP.
// ---------------------------------------------------------------------------
__global__ void __launch_bounds__(256) precompute_uM(
    const float* __restrict__ Wq, const float* __restrict__ Wp) {
  __shared__ float kk[4][D];
  __shared__ float vv[4][D];
  int h = blockIdx.y;
  int bg = blockIdx.z * 4;
  int c = blockIdx.x * 256 + threadIdx.x;
  if (threadIdx.x < 256) {
    int b = threadIdx.x >> 6, d = threadIdx.x & 63;
    kk[b][d] = g_k[(bg + b) * C + h * D + d];
    vv[b][d] = g_v[(bg + b) * C + h * D + d];
  }
  __syncthreads();

  float acc[4];
#pragma unroll
  for (int b = 0; b < 4; b++) acc[b] = 0.f;
#pragma unroll
  for (int d0 = 0; d0 < D; d0 += 16) {
    float wq[16];
#pragma unroll
    for (int j = 0; j < 16; j++) wq[j] = Wq[(h * D + d0 + j) * C + c];
#pragma unroll
    for (int j = 0; j < 16; j++)
#pragma unroll
      for (int b = 0; b < 4; b++) acc[b] += wq[j] * kk[b][d0 + j];
  }
#pragma unroll
  for (int b = 0; b < 4; b++) g_u[((bg + b) * H + h) * C + c] = acc[b];

  float acc2[4];
#pragma unroll
  for (int b = 0; b < 4; b++) acc2[b] = 0.f;
  const float4* wp4 = reinterpret_cast<const float4*>(Wp + c * C + h * D);
#pragma unroll
  for (int i0 = 0; i0 < 16; i0 += 8) {
    float4 wp[8];
#pragma unroll
    for (int i = 0; i < 8; i++) wp[i] = wp4[i0 + i];
#pragma unroll
    for (int i = 0; i < 8; i++) {
      int d = (i0 + i) * 4;
#pragma unroll
      for (int b = 0; b < 4; b++)
        acc2[b] += wp[i].x * vv[b][d] + wp[i].y * vv[b][d + 1] +
                   wp[i].z * vv[b][d + 2] + wp[i].w * vv[b][d + 3];
    }
  }
#pragma unroll
  for (int b = 0; b < 4; b++) g_M[((bg + b) * H + h) * C + c] = acc2[b];
}

// ---------------------------------------------------------------------------
// MAIN fused kernel. grid (128, 8), 256 threads, 32-row tile, 2 blocks/SM.
// u is staged per-chunk in the cp.async pipeline alongside fea (99KB smem).
// Phase 1: scores = fea_tile @ u[b]   (lane = row, warps split C)
// Phase 2: out = fea + bp + attn @ M[b]  with register prefetch pipeline.
// ---------------------------------------------------------------------------
#define ROWS 32
#define FB_STRIDE 260                    // floats per staged fea row (256 + 4)
#define FEA_FLOATS (ROWS * FB_STRIDE)    // 8320
#define U_FLOATS (H * 256)               // 4096 (u chunk [h][256])
#define STAGE_FLOATS (FEA_FLOATS + U_FLOATS)  // 12416
#define PART_STRIDE 17

__global__ void __launch_bounds__(256, 2) gate_main(
    const float* __restrict__ fea, const float* __restrict__ bp,
    float* __restrict__ out) {
  extern __shared__ __align__(16) float sm[];
  // Aliased scratch (safe: stage-0 fea last read at chunk 2, part written
  // after the final barrier of the chunk loop):
  float* part = sm;                                        // 8*32*17 = 4352 fl
  unsigned long long* attn_d =
      reinterpret_cast<unsigned long long*>(sm + 4352);    // 512 ull = 1024 fl

  const int b = blockIdx.y;
  const int row0 = blockIdx.x * ROWS;
  const int t = threadIdx.x;
  const int w = t >> 5;
  const int l = t & 31;

  const float* fea_b = fea + ((size_t)(b * N + row0)) * C;
  const float4* gu4 = reinterpret_cast<const float4*>(g_u + b * H * C);

  // ---- issue cp.async for one 256-col chunk (fea + u slice) into `buf` ----
#define ISSUE_CHUNK(ck, buf)                                                  \
  {                                                                           \
    float* sb = sm + (buf) * STAGE_FLOATS;                                    \
    _Pragma("unroll") for (int i = 0; i < 8; i++) {                           \
      int idx = t + 256 * i;                                                  \
      int r = idx >> 6;                                                       \
      int c4 = idx & 63;                                                      \
      const float* src = fea_b + r * C + (ck) * 256 + c4 * 4;                 \
      float* dstp = sb + r * FB_STRIDE + c4 * 4;                              \
      unsigned ds = (unsigned)__cvta_generic_to_shared(dstp);                 \
      asm volatile("cp.async.cg.shared.global [%0], [%1], 16;" ::"r"(ds),     \
                   "l"(src));                                                 \
    }                                                                         \
    _Pragma("unroll") for (int i = 0; i < 4; i++) {                           \
      int idx = t + 256 * i; /* idx = h*64 + j4 */                            \
      int h = idx >> 6;                                                       \
      int j4 = idx & 63;                                                      \
      const float4* srcu = gu4 + h * 256 + (ck) * 64 + j4;                    \
      float* dstp = sb + FEA_FLOATS + idx * 4;                                \
      unsigned ds = (unsigned)__cvta_generic_to_shared(dstp);                 \
      asm volatile("cp.async.cg.shared.global [%0], [%1], 16;" ::"r"(ds),     \
                   "l"(srcu));                                                \
    }                                                                         \
    asm volatile("cp.async.commit_group;" ::: "memory");                      \
  }

  unsigned long long p2[H];
#pragma unroll
  for (int h = 0; h < H; h++) p2[h] = 0ull;

  ISSUE_CHUNK(0, 0);
  ISSUE_CHUNK(1, 1);

#pragma unroll
  for (int ck = 0; ck < 4; ck++) {
    if (ck < 3)
      asm volatile("cp.async.wait_group 1;" ::: "memory");
    else
      asm volatile("cp.async.wait_group 0;" ::: "memory");
    __syncthreads();

    const float* sb = sm + (ck & 1) * STAGE_FLOATS;
    // warp w owns f4 cols [w*8, w*8+8) of this chunk, lane = row
    const float* fbp = sb + l * FB_STRIDE + w * 32;
    const float* uc = sb + FEA_FLOATS + w * 32;
#pragma unroll
    for (int j = 0; j < 8; j++) {
      ulonglong2 f = *reinterpret_cast<const ulonglong2*>(fbp + j * 4);
#pragma unroll
      for (int h = 0; h < H; h++) {
        ulonglong2 uu =
            *reinterpret_cast<const ulonglong2*>(uc + h * 256 + j * 4);
        FMA2(p2[h], f.x, uu.x);
        FMA2(p2[h], f.y, uu.y);
      }
    }
    __syncthreads();
    if (ck + 2 < 4) ISSUE_CHUNK(ck + 2, ck & 1);
  }

  // write per-warp partials: part[w][row=l][h]  (aliases stage-0 fea, now dead)
#pragma unroll
  for (int h = 0; h < H; h++) {
    float lo, hi;
    asm("mov.b64 {%0,%1}, %2;" : "=f"(lo), "=f"(hi) : "l"(p2[h]));
    part[(w * ROWS + l) * PART_STRIDE + h] = lo + hi;
  }
  __syncthreads();

  // reduce across 8 warps + sigmoid; store duplicated f32x2 attn
#pragma unroll
  for (int q = 0; q < 2; q++) {
    int p = t + q * 256;  // 0..511 == (r,h)
    int r = p >> 4;
    int h = p & 15;
    float s = 0.f;
#pragma unroll
    for (int ww = 0; ww < 8; ww++) s += part[(ww * ROWS + r) * PART_STRIDE + h];
    float a = 1.f / (1.f + __expf(-s * SCALE));
    unsigned long long ad;
    asm("mov.b64 %0, {%1,%1};" : "=l"(ad) : "f"(a));
    attn_d[r * H + h] = ad;
  }
  __syncthreads();

  // ---- Phase 2: out = fea + bp + attn @ M[b] ; thread owns 4 cols ----
  const int c0 = t * 4;
  const ulonglong2* attn2 = reinterpret_cast<const ulonglong2*>(attn_d);
  ulonglong2 bpv = *reinterpret_cast<const ulonglong2*>(bp + c0);
  ulonglong2 M2[H];
#pragma unroll
  for (int h = 0; h < H; h++)
    M2[h] = *reinterpret_cast<const ulonglong2*>(g_M + (b * H + h) * C + c0);

  float* out_b = out + ((size_t)(b * N + row0)) * C;

  // 2-row register prefetch pipeline (fea re-reads are L2 hits; keep 2 in flight)
  ulonglong2 pf0 = *reinterpret_cast<const ulonglong2*>(fea_b + 0 * C + c0);
  ulonglong2 pf1 = *reinterpret_cast<const ulonglong2*>(fea_b + 1 * C + c0);
#pragma unroll 4
  for (int r = 0; r < ROWS; r += 2) {
    ulonglong2 f0 = pf0, f1 = pf1;
    if (r + 2 < ROWS) {
      pf0 = *reinterpret_cast<const ulonglong2*>(fea_b + (r + 2) * C + c0);
      pf1 = *reinterpret_cast<const ulonglong2*>(fea_b + (r + 3) * C + c0);
    }
#pragma unroll
    for (int rr = 0; rr < 2; rr++) {
      ulonglong2 f = rr ? f1 : f0;
      unsigned long long oa, ob;
      ADD2(oa, f.x, bpv.x);
      ADD2(ob, f.y, bpv.y);
#pragma unroll
      for (int hg = 0; hg < 4; hg++) {
        ulonglong2 a0 = attn2[(r + rr) * 8 + hg * 2];
        ulonglong2 a1 = attn2[(r + rr) * 8 + hg * 2 + 1];
        FMA2(oa, a0.x, M2[hg * 4 + 0].x);
        FMA2(ob, a0.x, M2[hg * 4 + 0].y);
        FMA2(oa, a0.y, M2[hg * 4 + 1].x);
        FMA2(ob, a0.y, M2[hg * 4 + 1].y);
        FMA2(oa, a1.x, M2[hg * 4 + 2].x);
        FMA2(ob, a1.x, M2[hg * 4 + 2].y);
        FMA2(oa, a1.y, M2[hg * 4 + 3].x);
        FMA2(ob, a1.y, M2[hg * 4 + 3].y);
      }
      ulonglong2 o;
      o.x = oa;
      o.y = ob;
      *reinterpret_cast<ulonglong2*>(out_b + (r + rr) * C + c0) = o;
    }
  }
}

// ---------------------------------------------------------------------------
extern "C" void kernel_launch(void* const* d_in, const int* in_sizes, int n_in,
                              void* d_out, int out_size) {
  const float* fea = (const float*)d_in[0];
  const float* emb = (const float*)d_in[1];
  const float* Wq  = (const float*)d_in[2];
  const float* Wk  = (const float*)d_in[3];
  const float* Wv  = (const float*)d_in[4];
  const float* Wp  = (const float*)d_in[5];
  const float* bp  = (const float*)d_in[6];
  float* out = (float*)d_out;

  const int smem_main = 2 * STAGE_FLOATS * 4;  // 99328 bytes
  cudaFuncSetAttribute(gate_main, cudaFuncAttributeMaxDynamicSharedMemorySize,
                       smem_main);

  precompute_kv<<<256, 256>>>(emb, Wk, Wv);
  precompute_uM<<<dim3(4, 16, 2), 256>>>(Wq, Wp);
  gate_main<<<dim3(N / ROWS, B), 256, smem_main>>>(fea, bp, out);
}

// round 4
// speedup vs baseline: 1.4215x; 1.0033x over previous
#include <cuda_runtime.h>
#include <cstdint>

// Problem constants
#define B 8
#define N 4096
#define C 1024
#define H 16
#define D 64
#define SCALE 0.125f

typedef unsigned long long ull;

// Scratch (no cudaMalloc allowed)
__device__ float g_k[B * C];       // [b][h*D+d]
__device__ float g_v[B * C];
__device__ float g_u[B * H * C];   // [b][h][c]  folded Wq*k
__device__ float g_M[B * H * C];   // [b][h][c]  folded Wp*v

// Packed fp32x2 helpers (sm_103a)
#define FMA2(acc, a, bb) asm("fma.rn.f32x2 %0, %1, %2, %0;" : "+l"(acc) : "l"(a), "l"(bb))
#define ADD2(d, a, bb)   asm("add.rn.f32x2 %0, %1, %2;"     : "=l"(d)   : "l"(a), "l"(bb))

// Volatile vector/scalar loads: ptxas cannot sink these into dependent code,
// guaranteeing the front-batched MLP we want.
#define LDGV4(dst, ptr)                                                     \
  asm volatile("ld.global.nc.v4.f32 {%0,%1,%2,%3}, [%4];"                   \
               : "=f"(dst.x), "=f"(dst.y), "=f"(dst.z), "=f"(dst.w)         \
               : "l"(ptr))
#define LDGF(dst, ptr) \
  asm volatile("ld.global.nc.f32 %0, [%1];" : "=f"(dst) : "l"(ptr))

#define CPASYNC16(smem_u32, gptr)                                           \
  asm volatile("cp.async.cg.shared.global [%0], [%1], 16;" ::"r"(smem_u32), \
               "l"(gptr))
#define COMMIT() asm volatile("cp.async.commit_group;" ::: "memory")
#define WAITG(n) asm volatile("cp.async.wait_group %0;" ::"n"(n) : "memory")

// ---------------------------------------------------------------------------
// P1: k = emb @ Wk.T, v = emb @ Wv.T.
// 4096 warps: warp = (matrix, j, batch-half). Volatile front-batched W row.
// ---------------------------------------------------------------------------
__global__ void __launch_bounds__(128) precompute_kv(
    const float* __restrict__ emb, const float* __restrict__ Wk,
    const float* __restrict__ Wv) {
  int gw = (blockIdx.x * 128 + threadIdx.x) >> 5;  // 0..4095
  int lane = threadIdx.x & 31;
  int sel = gw >> 11;
  int rem = gw & 2047;
  int j = rem >> 1;
  int bh = (rem & 1) * 4;
  const float* W = sel ? Wv : Wk;
  float* dst = sel ? g_v : g_k;
  const float4* w4 = reinterpret_cast<const float4*>(W + j * C);
  const float4* e4 = reinterpret_cast<const float4*>(emb);

  float4 wv[8];
#pragma unroll
  for (int i = 0; i < 8; i++) LDGV4(wv[i], w4 + lane + 32 * i);

  float acc[4];
#pragma unroll
  for (int b = 0; b < 4; b++) acc[b] = 0.f;
#pragma unroll
  for (int b = 0; b < 4; b++) {
    float4 e[8];
#pragma unroll
    for (int i = 0; i < 8; i++) e[i] = e4[(bh + b) * 256 + lane + 32 * i];
#pragma unroll
    for (int i = 0; i < 8; i++)
      acc[b] += wv[i].x * e[i].x + wv[i].y * e[i].y + wv[i].z * e[i].z +
                wv[i].w * e[i].w;
  }
#pragma unroll
  for (int b = 0; b < 4; b++)
    for (int s = 16; s; s >>= 1) acc[b] += __shfl_xor_sync(0xffffffffu, acc[b], s);
  if (lane == 0) {
#pragma unroll
    for (int b = 0; b < 4; b++) dst[(bh + b) * C + j] = acc[b];
  }
}

// ---------------------------------------------------------------------------
// P2: u[b,h,c] = sum_d Wq[h*64+d, c] * k[b,h*64+d]
//     M[b,h,c] = sum_d Wp[c, h*64+d] * v[b,h*64+d]
// grid (4, 16, 8): x = c-block, y = h, z = batch. 512 blocks, 27.7 warps/SM.
// ---------------------------------------------------------------------------
__global__ void __launch_bounds__(256) precompute_uM(
    const float* __restrict__ Wq, const float* __restrict__ Wp) {
  __shared__ float kk[D];
  __shared__ float vv[D];
  int h = blockIdx.y;
  int b = blockIdx.z;
  int c = blockIdx.x * 256 + threadIdx.x;
  if (threadIdx.x < 64)
    kk[threadIdx.x] = g_k[b * C + h * D + threadIdx.x];
  else if (threadIdx.x < 128)
    vv[threadIdx.x - 64] = g_v[b * C + h * D + threadIdx.x - 64];
  __syncthreads();

  float acc = 0.f;
#pragma unroll
  for (int d0 = 0; d0 < D; d0 += 16) {
    float wq[16];
#pragma unroll
    for (int jj = 0; jj < 16; jj++) LDGF(wq[jj], Wq + (h * D + d0 + jj) * C + c);
#pragma unroll
    for (int jj = 0; jj < 16; jj++) acc += wq[jj] * kk[d0 + jj];
  }
  g_u[(b * H + h) * C + c] = acc;

  float acc2 = 0.f;
  const float4* wp4 = reinterpret_cast<const float4*>(Wp + c * C + h * D);
#pragma unroll
  for (int i0 = 0; i0 < 16; i0 += 8) {
    float4 wp[8];
#pragma unroll
    for (int i = 0; i < 8; i++) LDGV4(wp[i], wp4 + i0 + i);
#pragma unroll
    for (int i = 0; i < 8; i++) {
      int d = (i0 + i) * 4;
      acc2 += wp[i].x * vv[d] + wp[i].y * vv[d + 1] + wp[i].z * vv[d + 2] +
              wp[i].w * vv[d + 3];
    }
  }
  g_M[(b * H + h) * C + c] = acc2;
}

// ---------------------------------------------------------------------------
// MAIN persistent kernel. 148 blocks (1/SM), 256 threads.
// smem: u[b] (64KB) + full 32x1024 fea tile (131.5KB) + part/attn scratch.
// Each block owns ~7 contiguous tiles; u/M reloaded only on batch change.
// Phase 1: scores from smem fea chunks as cp.async lands (lane=row, u bcast).
// Phase 2: out = fea(smem) + bp + attn @ M(regs).  No global fea re-read.
// ---------------------------------------------------------------------------
#define ROWS 32
#define FSTR 1028
#define NBLK 148
#define TILES (B * N / ROWS)  // 1024
#define U_FLOATS (H * C)                    // 16384
#define FEA_FLOATS (ROWS * FSTR)            // 32896
#define PART_FLOATS (8 * ROWS * 17)         // 4352
#define SMEM_FLOATS (U_FLOATS + FEA_FLOATS + PART_FLOATS + ROWS * H * 2)

__global__ void __launch_bounds__(256, 1) gate_main(
    const float* __restrict__ fea, const float* __restrict__ bp,
    float* __restrict__ out) {
  extern __shared__ __align__(16) float sm[];
  float* u_s = sm;                              // [h][c] 16384
  float* fea_s = sm + U_FLOATS;                 // [r][FSTR]
  float* part = fea_s + FEA_FLOATS;             // [w][r][17]
  ull* attn_d = reinterpret_cast<ull*>(part + PART_FLOATS);  // [r][h]

  const int t = threadIdx.x;
  const int w = t >> 5;
  const int l = t & 31;
  const int c0 = t * 4;

  const int t_start = (blockIdx.x * TILES) / NBLK;
  const int t_end = ((blockIdx.x + 1) * TILES) / NBLK;

  ulonglong2 bpv = *reinterpret_cast<const ulonglong2*>(bp + c0);
  ulonglong2 M2[H];
  int cur_b = -1;

  for (int tile = t_start; tile < t_end; ++tile) {
    const int b = tile >> 7;
    const int row0 = (tile & 127) * ROWS;
    const float* fea_b = fea + ((size_t)(b * N + row0)) * C;

    if (b != cur_b) {
      cur_b = b;
      // u[b] -> smem (cp.async, own group, committed before fea groups)
      const float4* gu4 = reinterpret_cast<const float4*>(g_u + b * H * C);
#pragma unroll
      for (int i = 0; i < 16; i++) {
        int idx = t + 256 * i;
        unsigned ds = (unsigned)__cvta_generic_to_shared(u_s + idx * 4);
        CPASYNC16(ds, gu4 + idx);
      }
      COMMIT();
      // M[b] column slice -> regs
#pragma unroll
      for (int h = 0; h < H; h++)
        M2[h] = *reinterpret_cast<const ulonglong2*>(g_M + (b * H + h) * C + c0);
    }

    // Issue the whole fea tile (4 chunk groups, 128KB in flight)
#pragma unroll
    for (int ck = 0; ck < 4; ck++) {
#pragma unroll
      for (int i = 0; i < 8; i++) {
        int idx = t + 256 * i;
        int r = idx >> 6;
        int c4 = idx & 63;
        const float* src = fea_b + r * C + ck * 256 + c4 * 4;
        unsigned ds = (unsigned)__cvta_generic_to_shared(
            fea_s + r * FSTR + ck * 256 + c4 * 4);
        CPASYNC16(ds, src);
      }
      COMMIT();
    }

    // ---- Phase 1: scores ----
    ull p2[H];
#pragma unroll
    for (int h = 0; h < H; h++) p2[h] = 0ull;

#pragma unroll
    for (int ck = 0; ck < 4; ck++) {
      if (ck == 0) WAITG(3);
      else if (ck == 1) WAITG(2);
      else if (ck == 2) WAITG(1);
      else WAITG(0);
      __syncthreads();

      const float* fp = fea_s + l * FSTR + ck * 256 + w * 32;
      const float* up = u_s + ck * 256 + w * 32;
#pragma unroll
      for (int j = 0; j < 8; j++) {
        ulonglong2 f = *reinterpret_cast<const ulonglong2*>(fp + j * 4);
#pragma unroll
        for (int h = 0; h < H; h++) {
          ulonglong2 uu =
              *reinterpret_cast<const ulonglong2*>(up + h * C + j * 4);
          FMA2(p2[h], f.x, uu.x);
          FMA2(p2[h], f.y, uu.y);
        }
      }
    }

    // per-warp partials: part[w][row=l][h]
#pragma unroll
    for (int h = 0; h < H; h++) {
      float lo, hi;
      asm("mov.b64 {%0,%1}, %2;" : "=f"(lo), "=f"(hi) : "l"(p2[h]));
      part[(w * ROWS + l) * 17 + h] = lo + hi;
    }
    __syncthreads();

    // reduce 8 warps + sigmoid -> duplicated f32x2 attn
#pragma unroll
    for (int q = 0; q < 2; q++) {
      int p = t + q * 256;  // (r,h)
      int r = p >> 4;
      int h = p & 15;
      float s = 0.f;
#pragma unroll
      for (int ww = 0; ww < 8; ww++) s += part[(ww * ROWS + r) * 17 + h];
      float a = 1.f / (1.f + __expf(-s * SCALE));
      ull ad;
      asm("mov.b64 %0, {%1,%1};" : "=l"(ad) : "f"(a));
      attn_d[r * H + h] = ad;
    }
    __syncthreads();

    // ---- Phase 2: out = fea(smem) + bp + attn @ M2 ----
    float* out_b = out + ((size_t)(b * N + row0)) * C;
#pragma unroll 4
    for (int r = 0; r < ROWS; r++) {
      ulonglong2 f = *reinterpret_cast<const ulonglong2*>(fea_s + r * FSTR + c0);
      ull oa, ob;
      ADD2(oa, f.x, bpv.x);
      ADD2(ob, f.y, bpv.y);
#pragma unroll
      for (int hg = 0; hg < 4; hg++) {
        ulonglong2 a0 =
            *reinterpret_cast<const ulonglong2*>(attn_d + r * H + hg * 4);
        ulonglong2 a1 =
            *reinterpret_cast<const ulonglong2*>(attn_d + r * H + hg * 4 + 2);
        FMA2(oa, a0.x, M2[hg * 4 + 0].x);
        FMA2(ob, a0.x, M2[hg * 4 + 0].y);
        FMA2(oa, a0.y, M2[hg * 4 + 1].x);
        FMA2(ob, a0.y, M2[hg * 4 + 1].y);
        FMA2(oa, a1.x, M2[hg * 4 + 2].x);
        FMA2(ob, a1.x, M2[hg * 4 + 2].y);
        FMA2(oa, a1.y, M2[hg * 4 + 3].x);
        FMA2(ob, a1.y, M2[hg * 4 + 3].y);
      }
      ulonglong2 o;
      o.x = oa;
      o.y = ob;
      *reinterpret_cast<ulonglong2*>(out_b + r * C + c0) = o;
    }
    __syncthreads();  // release fea_s/u_s before next tile's cp.async
  }
}

// ---------------------------------------------------------------------------
extern "C" void kernel_launch(void* const* d_in, const int* in_sizes, int n_in,
                              void* d_out, int out_size) {
  const float* fea = (const float*)d_in[0];
  const float* emb = (const float*)d_in[1];
  const float* Wq  = (const float*)d_in[2];
  const float* Wk  = (const float*)d_in[3];
  const float* Wv  = (const float*)d_in[4];
  const float* Wp  = (const float*)d_in[5];
  const float* bp  = (const float*)d_in[6];
  float* out = (float*)d_out;

  const int smem_main = SMEM_FLOATS * 4;  // 218624 bytes
  cudaFuncSetAttribute(gate_main, cudaFuncAttributeMaxDynamicSharedMemorySize,
                       smem_main);

  precompute_kv<<<1024, 128>>>(emb, Wk, Wv);
  precompute_uM<<<dim3(4, H, B), 256>>>(Wq, Wp);
  gate_main<<<NBLK, 256, smem_main>>>(fea, bp, out);
}